// round 1
// baseline (speedup 1.0000x reference)
#include <cuda_runtime.h>
#include <cuda_bf16.h>

// DenseFeatureNumericEmbedding: emb[b,f,e] = b2[f,e] + sum_h W2[f,e,h]*relu(x[b,f]*W1[f,h]+b1[f,h])
// Piecewise-linear-in-x formulation: per f, 65 segments of (A,C): emb = A*x + C.
// Kernel 1 builds per-feature segment tables; kernel 2 evaluates with a bucket LUT.

#define BN 16384
#define FN 128
#define HN 64
#define EN 16

// bucket map constants (must be used IDENTICALLY in both kernels)
#define BUCK_LO (-6.0f)
#define BUCK_SC (256.0f / 12.0f)

// Scratch (allocation-free): per-feature tables.
// g_tabflat layout per f: 65 segs * 32 floats; within a seg: 8 groups of
// [A_{2e2}, C_{2e2}, A_{2e2+1}, C_{2e2+1}] (float4-friendly).
__device__ float          g_tabflat[FN * 65 * 32];
__device__ float          g_thr[FN * 64];
__device__ unsigned char  g_lut[FN * 257];

__device__ __forceinline__ int bucket_of(float v) {
    float p = (v - BUCK_LO) * BUCK_SC;
    p = fminf(fmaxf(p, 0.0f), 255.0f);   // handles +/-inf sentinels too
    return (int)p;                        // trunc == floor for p >= 0
}

// ---------------------------------------------------------------------------
// Kernel 1: per-feature precompute. One block per f.
// ---------------------------------------------------------------------------
__global__ void __launch_bounds__(128) dfe_precompute(
    const float* __restrict__ W1, const float* __restrict__ b1,
    const float* __restrict__ W2, const float* __restrict__ b2)
{
    int f = blockIdx.x;
    int tid = threadIdx.x;

    __shared__ float sw[HN], sb[HN], tv_[HN], st[HN];
    __shared__ int   sidx[HN];

    if (tid < HN) {
        float w = W1[f * HN + tid];
        float b = b1[f * HN + tid];
        sw[tid] = w; sb[tid] = b;
        // threshold of the relu hinge; w==0 -> sentinel at +huge (never crossed)
        float tv = (w != 0.0f) ? (-b / w) : 3.0e38f;
        tv_[tid] = tv;
    }
    __syncthreads();

    // rank-sort 64 thresholds (stable via index tie-break)
    if (tid < HN) {
        float tv = tv_[tid];
        int r = 0;
        for (int j = 0; j < HN; j++) {
            float tj = tv_[j];
            r += (tj < tv) || (tj == tv && j < tid);
        }
        st[r] = tv;
        sidx[r] = tid;
    }
    __syncthreads();

    if (tid < HN) g_thr[f * HN + tid] = st[tid];

    // LUT: lut[k] = #{ thresholds with bucket < k }, k in [0,256]
    for (int k = tid; k < 257; k += blockDim.x) {
        int c = 0;
        for (int j = 0; j < HN; j++) c += (bucket_of(st[j]) < k);
        g_lut[f * 257 + k] = (unsigned char)c;
    }

    // Segment table walk: 16 threads, one per e.
    if (tid < EN) {
        int e = tid;
        const float* w2 = W2 + (f * EN + e) * HN;
        // Base state at x = -inf: active set = { h : w < 0 }.
        float A = 0.0f;
        float C = b2[f * EN + e];
        for (int h = 0; h < HN; h++) {
            float w = sw[h], b = sb[h], v = w2[h];
            if (w < 0.0f)       { A += w * v; C += b * v; }
            else if (w == 0.0f) { C += fmaxf(b, 0.0f) * v; }   // constant contribution
        }
        float* dst = g_tabflat + f * (65 * 32);
        int e2 = e >> 1, comp = (e & 1) * 2;
        for (int s = 0; s <= 64; s++) {
            dst[s * 32 + e2 * 4 + comp]     = A;
            dst[s * 32 + e2 * 4 + comp + 1] = C;
            if (s < 64) {
                int h = sidx[s];
                float w = sw[h], b = sb[h], v = w2[h];
                if (w > 0.0f)      { A += w * v; C += b * v; }  // turns ON at t
                else if (w < 0.0f) { A -= w * v; C -= b * v; }  // turns OFF at t
                // w==0: sentinel, never reached (seg <= count(t<=x) < its rank)
            }
        }
    }
}

// ---------------------------------------------------------------------------
// Kernel 2: evaluation. Block = 2 features x 512 batch rows (4 iters of 128).
// grid = (FN/2 = 64, BN/512 = 32), 128 threads.
// ---------------------------------------------------------------------------
__global__ void __launch_bounds__(128) dfe_eval(
    const float* __restrict__ x, float* __restrict__ out)
{
    __shared__ float4        stab[2][65 * 8];   // swizzled segment tables
    __shared__ float         sthr[2][64];
    __shared__ unsigned char slut[2][260];
    __shared__ float4        tile[128 * 8];     // output staging (XOR-swizzled)

    int tid = threadIdx.x;
    int fp  = blockIdx.x;               // feature pair index
    int bbase = blockIdx.y * 512;

    // Load both feature tables into smem with XOR swizzle on the e2 slot.
    for (int i = tid; i < 2 * 2080; i += 128) {
        int ff = i / 2080, r = i % 2080;
        int s = r / 32, w = r % 32;
        int e2 = w >> 2, comp = w & 3;
        ((float*)&stab[ff][0])[s * 32 + ((e2 ^ (s & 7)) << 2) + comp] =
            g_tabflat[(fp * 2 + ff) * 2080 + r];
    }
    for (int i = tid; i < 2 * 64; i += 128) {
        int ff = i >> 6, j = i & 63;
        sthr[ff][j] = g_thr[(fp * 2 + ff) * 64 + j];
    }
    for (int i = tid; i < 2 * 257; i += 128) {
        int ff = i / 257, j = i % 257;
        slut[ff][j] = g_lut[(fp * 2 + ff) * 257 + j];
    }
    __syncthreads();

    for (int it = 0; it < 4; it++) {
        int b = bbase + it * 128 + tid;
        float2 xv = *(const float2*)(x + (size_t)b * FN + fp * 2);

        float o[32];
        #pragma unroll
        for (int ff = 0; ff < 2; ff++) {
            float xs = ff ? xv.y : xv.x;
            int k = bucket_of(xs);
            int s0 = slut[ff][k];
            int s1 = slut[ff][k + 1];
            int seg = s0;
            for (int j = s0; j < s1; j++) seg += (sthr[ff][j] <= xs);

            const float4* row = &stab[ff][seg * 8];
            int sw = seg & 7;
            #pragma unroll
            for (int e2 = 0; e2 < 8; e2++) {
                float4 v = row[e2 ^ sw];
                o[ff * 16 + e2 * 2]     = fmaf(v.x, xs, v.y);
                o[ff * 16 + e2 * 2 + 1] = fmaf(v.z, xs, v.w);
            }
        }

        // Stage this thread's 32 outputs (one row of the [128 x 32] tile).
        #pragma unroll
        for (int c4 = 0; c4 < 8; c4++) {
            tile[tid * 8 + (c4 ^ (tid & 7))] =
                make_float4(o[c4 * 4], o[c4 * 4 + 1], o[c4 * 4 + 2], o[c4 * 4 + 3]);
        }
        __syncthreads();

        // Coalesced write-out: consecutive lanes -> consecutive 16B chunks.
        #pragma unroll
        for (int p = 0; p < 8; p++) {
            int idx = p * 128 + tid;
            int row = idx >> 3, c4 = idx & 7;
            float4 v = tile[row * 8 + (c4 ^ (row & 7))];
            *(float4*)(out + (size_t)(bbase + it * 128 + row) * (FN * EN)
                           + fp * 32 + c4 * 4) = v;
        }
        __syncthreads();
    }
}

extern "C" void kernel_launch(void* const* d_in, const int* in_sizes, int n_in,
                              void* d_out, int out_size)
{
    const float* x  = (const float*)d_in[0];
    const float* W1 = (const float*)d_in[1];
    const float* b1 = (const float*)d_in[2];
    const float* W2 = (const float*)d_in[3];
    const float* b2 = (const float*)d_in[4];
    float* out = (float*)d_out;

    dfe_precompute<<<FN, 128>>>(W1, b1, W2, b2);
    dfe_eval<<<dim3(FN / 2, BN / 512), 128>>>(x, out);
}